// round 1
// baseline (speedup 1.0000x reference)
#include <cuda_runtime.h>
#include <cuda_bf16.h>
#include <cstdint>

// ---------------------------------------------------------------------------
// NSHE: 3x (feat @ W + b, relu) -> concat -> (enc @ gcnW + gcnb) ->
//       edge gather*w scatter-add -> row L2 normalize
// Shapes: N_A=100000 K=512, N_B=60000 K=256, N_C=40000 K=128, D=64, E=3.2M
// ---------------------------------------------------------------------------

#define D 64
#define KT 64                    // K-chunk staged in smem
#define ROWS_PER_WARP 4
#define WARPS_PER_BLOCK 8
#define ROWS_PER_BLOCK (ROWS_PER_WARP * WARPS_PER_BLOCK)   // 32
#define MAX_N 200000

__device__ float g_enc[(size_t)MAX_N * D];      // encoder outputs (concat)
__device__ float g_support[(size_t)MAX_N * D];  // enc @ gcn_W + gcn_b

// packed f32x2 FMA (2x fp32 throughput vs 3-reg FFMA on sm_103a)
__device__ __forceinline__ unsigned long long ffma2(unsigned long long a,
                                                    unsigned long long b,
                                                    unsigned long long c) {
    unsigned long long d;
    asm("fma.rn.f32x2 %0, %1, %2, %3;" : "=l"(d) : "l"(a), "l"(b), "l"(c));
    return d;
}

__device__ __forceinline__ unsigned long long pack2(float f) {
    unsigned long long p;
    asm("mov.b64 %0, {%1, %1};" : "=l"(p) : "f"(f));
    return p;
}

// ---------------------------------------------------------------------------
// GEMM body: out[row][0:64] = act(feat[row][0:K] @ W[K][64] + b)
// 256 threads; warp handles 4 rows x 64 cols (each lane: 4 rows x 2 cols as
// f32x2 accumulators). W staged through smem in KT=64 chunks; feat values
// broadcast across the warp via shfl.
// ---------------------------------------------------------------------------
__device__ __forceinline__ void gemm_body(const float* __restrict__ feat,
                                          const float* __restrict__ W,
                                          const float* __restrict__ bias,
                                          float* __restrict__ out,
                                          int nrows, int K, int do_relu) {
    __shared__ float sW[KT][D];  // 16 KB

    const int warp = threadIdx.x >> 5;
    const int lane = threadIdx.x & 31;
    const int row0 = blockIdx.x * ROWS_PER_BLOCK + warp * ROWS_PER_WARP;

    unsigned long long acc[ROWS_PER_WARP] = {0ull, 0ull, 0ull, 0ull};

    for (int k0 = 0; k0 < K; k0 += KT) {
        __syncthreads();
        // cooperative load of W chunk: KT*D floats = 1024 float4
        {
            const float4* src = (const float4*)(W + (size_t)k0 * D);
            float4* dst = (float4*)(&sW[0][0]);
            #pragma unroll
            for (int i = 0; i < (KT * D / 4) / 256; ++i)
                dst[threadIdx.x + i * 256] = src[threadIdx.x + i * 256];
        }
        __syncthreads();

        #pragma unroll
        for (int h = 0; h < KT / 32; ++h) {
            float fv[ROWS_PER_WARP];
            #pragma unroll
            for (int r = 0; r < ROWS_PER_WARP; ++r) {
                int row = row0 + r;
                fv[r] = (row < nrows) ? feat[(size_t)row * K + k0 + h * 32 + lane] : 0.0f;
            }
            #pragma unroll
            for (int kk = 0; kk < 32; ++kk) {
                unsigned long long w2 =
                    *(const unsigned long long*)&sW[h * 32 + kk][lane * 2];
                #pragma unroll
                for (int r = 0; r < ROWS_PER_WARP; ++r) {
                    float f = __shfl_sync(0xffffffffu, fv[r], kk);
                    acc[r] = ffma2(pack2(f), w2, acc[r]);
                }
            }
        }
    }

    const float2 bv = *(const float2*)&bias[lane * 2];
    #pragma unroll
    for (int r = 0; r < ROWS_PER_WARP; ++r) {
        int row = row0 + r;
        if (row >= nrows) continue;
        float2 a = *(float2*)&acc[r];
        a.x += bv.x; a.y += bv.y;
        if (do_relu) { a.x = fmaxf(a.x, 0.0f); a.y = fmaxf(a.y, 0.0f); }
        *(float2*)&out[(size_t)row * D + lane * 2] = a;
    }
}

__global__ void enc_gemm_kernel(const float* __restrict__ feat,
                                const float* __restrict__ W,
                                const float* __restrict__ b,
                                int row_off, int nrows, int K) {
    gemm_body(feat, W, b, g_enc + (size_t)row_off * D, nrows, K, 1);
}

__global__ void gcn_gemm_kernel(const float* __restrict__ W,
                                const float* __restrict__ b, int nrows) {
    gemm_body(g_enc, W, b, g_support, nrows, D, 0);
}

// ---------------------------------------------------------------------------
// Scatter: out[dst] += support[src] * w   (16 threads/edge, one float4 each,
// vectorized red.global.add.v4.f32 -> 4x fewer atomic ops)
// ---------------------------------------------------------------------------
__global__ void scatter_kernel(const int* __restrict__ esrc,
                               const int* __restrict__ edst,
                               const float* __restrict__ ew,
                               float* __restrict__ out, int E) {
    unsigned idx = blockIdx.x * blockDim.x + threadIdx.x;
    int e = idx >> 4;
    int c = idx & 15;
    if (e >= E) return;
    int s = __ldg(&esrc[e]);
    int d = __ldg(&edst[e]);
    float w = __ldg(&ew[e]);
    float4 v = *(const float4*)&g_support[(size_t)s * D + c * 4];
    v.x *= w; v.y *= w; v.z *= w; v.w *= w;
    float* p = &out[(size_t)d * D + c * 4];
    asm volatile("red.global.add.v4.f32 [%0], {%1, %2, %3, %4};"
                 :: "l"(p), "f"(v.x), "f"(v.y), "f"(v.z), "f"(v.w)
                 : "memory");
}

// ---------------------------------------------------------------------------
// Row L2 normalize (warp per row)
// ---------------------------------------------------------------------------
__global__ void normalize_kernel(float* __restrict__ out, int N) {
    int row = blockIdx.x * (blockDim.x >> 5) + (threadIdx.x >> 5);
    int lane = threadIdx.x & 31;
    if (row >= N) return;
    float2 v = *(float2*)&out[(size_t)row * D + lane * 2];
    float s = v.x * v.x + v.y * v.y;
    #pragma unroll
    for (int o = 16; o > 0; o >>= 1) s += __shfl_xor_sync(0xffffffffu, s, o);
    float n = sqrtf(s);
    float sc = 1.0f / fmaxf(n, 1e-12f);
    v.x *= sc; v.y *= sc;
    *(float2*)&out[(size_t)row * D + lane * 2] = v;
}

// ---------------------------------------------------------------------------
// launch
// ---------------------------------------------------------------------------
extern "C" void kernel_launch(void* const* d_in, const int* in_sizes, int n_in,
                              void* d_out, int out_size) {
    const float* feat_a = (const float*)d_in[0];
    const float* W_a    = (const float*)d_in[1];
    const float* b_a    = (const float*)d_in[2];
    const float* feat_b = (const float*)d_in[3];
    const float* W_b    = (const float*)d_in[4];
    const float* b_b    = (const float*)d_in[5];
    const float* feat_c = (const float*)d_in[6];
    const float* W_c    = (const float*)d_in[7];
    const float* b_c    = (const float*)d_in[8];
    const float* gcn_W  = (const float*)d_in[9];
    const float* gcn_b  = (const float*)d_in[10];
    const float* ew     = (const float*)d_in[11];
    const int*   esrc   = (const int*)d_in[12];
    const int*   edst   = (const int*)d_in[13];
    float* out = (float*)d_out;

    const int Ka = in_sizes[1] / D, Na = in_sizes[0] / Ka;
    const int Kb = in_sizes[4] / D, Nb = in_sizes[3] / Kb;
    const int Kc = in_sizes[7] / D, Nc = in_sizes[6] / Kc;
    const int E  = in_sizes[11];
    const int N  = Na + Nb + Nc;

    dim3 blk(256);

    // 1) encoders -> g_enc (concat layout)
    enc_gemm_kernel<<<(Na + ROWS_PER_BLOCK - 1) / ROWS_PER_BLOCK, blk>>>(
        feat_a, W_a, b_a, 0, Na, Ka);
    enc_gemm_kernel<<<(Nb + ROWS_PER_BLOCK - 1) / ROWS_PER_BLOCK, blk>>>(
        feat_b, W_b, b_b, Na, Nb, Kb);
    enc_gemm_kernel<<<(Nc + ROWS_PER_BLOCK - 1) / ROWS_PER_BLOCK, blk>>>(
        feat_c, W_c, b_c, Na + Nb, Nc, Kc);

    // 2) gcn linear -> g_support
    gcn_gemm_kernel<<<(N + ROWS_PER_BLOCK - 1) / ROWS_PER_BLOCK, blk>>>(
        gcn_W, gcn_b, N);

    // 3) zero output, then edge scatter-add
    cudaMemsetAsync(d_out, 0, (size_t)out_size * sizeof(float));
    {
        long long threads = (long long)E * 16;
        int grid = (int)((threads + 255) / 256);
        scatter_kernel<<<grid, blk>>>(esrc, edst, ew, out, E);
    }

    // 4) row L2 normalize
    normalize_kernel<<<(N + 7) / 8, blk>>>(out, N);
}

// round 2
// speedup vs baseline: 1.4262x; 1.4262x over previous
#include <cuda_runtime.h>
#include <cuda_bf16.h>
#include <cstdint>

// ---------------------------------------------------------------------------
// NSHE: 3x (feat @ W + b, relu) -> concat -> (enc @ gcnW + gcnb) ->
//       edge gather*w scatter-add -> row L2 normalize
// ---------------------------------------------------------------------------

#define D 64
#define MAX_N 200000

// GEMM tiling
#define BM 128
#define BN 64
#define BK 16
#define PA 4
#define PB 4
#define SA_STRIDE (BM + PA)   // 132 floats
#define SB_STRIDE (BN + PB)   // 68 floats
#define NTHREADS 256

__device__ float g_enc[(size_t)MAX_N * D];      // encoder outputs (concat)
__device__ float g_support[(size_t)MAX_N * D];  // enc @ gcn_W + gcn_b

typedef unsigned long long u64;

// packed f32x2 FMA (2x fp32 throughput on sm_103a fma pipe)
__device__ __forceinline__ u64 ffma2(u64 a, u64 b, u64 c) {
    u64 d;
    asm("fma.rn.f32x2 %0, %1, %2, %3;" : "=l"(d) : "l"(a), "l"(b), "l"(c));
    return d;
}
__device__ __forceinline__ u64 pack2(float f) {
    u64 p;
    asm("mov.b64 %0, {%1, %1};" : "=l"(p) : "f"(f));
    return p;
}
__device__ __forceinline__ float2 unpk(u64 v) {
    float2 r;
    asm("mov.b64 {%0, %1}, %2;" : "=f"(r.x), "=f"(r.y) : "l"(v));
    return r;
}

// ---------------------------------------------------------------------------
// Register-blocked tiled SGEMM: out[BMxBN tile] = act(feat @ W + b)
// 256 threads; each thread: 8 rows x 4 cols as f32x2 row-pair accumulators.
// A transposed in smem so LDS.128 delivers 4 consecutive rows (2 row-pairs).
// ---------------------------------------------------------------------------
__device__ __forceinline__ void gemm_body(const float* __restrict__ feat,
                                          const float* __restrict__ W,
                                          const float* __restrict__ bias,
                                          float* __restrict__ out,
                                          int nrows, int K, int do_relu) {
    __shared__ float sA[2][BK][SA_STRIDE];   // 2 x 8448 B
    __shared__ float sB[2][BK][SB_STRIDE];   // 2 x 4352 B

    const int tid = threadIdx.x;
    const int tx = tid & 15;          // col group -> c0
    const int ty = tid >> 4;          // row group -> r0
    const int c0 = tx * 4;
    const int r0 = ty * 8;
    const int blockRow = blockIdx.x * BM;

    // A global-load mapping: 2 float4 per thread (rows la_row0, la_row0+64)
    const int la_row0 = tid >> 2;           // 0..63
    const int la_k    = (tid & 3) * 4;      // 0,4,8,12
    // B global-load mapping: 1 float4 per thread
    const int lb_k = tid >> 4;              // 0..15
    const int lb_n = (tid & 15) * 4;

    const int rowA0 = min(blockRow + la_row0,      nrows - 1);
    const int rowA1 = min(blockRow + 64 + la_row0, nrows - 1);

    u64 acc[4][4];
    #pragma unroll
    for (int i = 0; i < 4; ++i)
        #pragma unroll
        for (int j = 0; j < 4; ++j) acc[i][j] = 0ull;

    const int ntiles = K / BK;

    // prefetch tile 0
    float4 pa0 = *(const float4*)&feat[(size_t)rowA0 * K + la_k];
    float4 pa1 = *(const float4*)&feat[(size_t)rowA1 * K + la_k];
    float4 pbv = *(const float4*)&W[(size_t)lb_k * D + lb_n];

    // store tile 0 into buffer 0 (A transposed)
    {
        sA[0][la_k + 0][la_row0] = pa0.x;
        sA[0][la_k + 1][la_row0] = pa0.y;
        sA[0][la_k + 2][la_row0] = pa0.z;
        sA[0][la_k + 3][la_row0] = pa0.w;
        sA[0][la_k + 0][la_row0 + 64] = pa1.x;
        sA[0][la_k + 1][la_row0 + 64] = pa1.y;
        sA[0][la_k + 2][la_row0 + 64] = pa1.z;
        sA[0][la_k + 3][la_row0 + 64] = pa1.w;
        *(float4*)&sB[0][lb_k][lb_n] = pbv;
    }
    __syncthreads();

    for (int t = 0; t < ntiles; ++t) {
        const int cur = t & 1;
        const int nxt = cur ^ 1;
        float4 na0, na1, nb;
        const bool more = (t + 1 < ntiles);
        if (more) {
            const int kt = (t + 1) * BK;
            na0 = *(const float4*)&feat[(size_t)rowA0 * K + kt + la_k];
            na1 = *(const float4*)&feat[(size_t)rowA1 * K + kt + la_k];
            nb  = *(const float4*)&W[(size_t)(kt + lb_k) * D + lb_n];
        }

        #pragma unroll
        for (int k = 0; k < BK; ++k) {
            ulonglong2 aP01 = *(const ulonglong2*)&sA[cur][k][r0];
            ulonglong2 aP23 = *(const ulonglong2*)&sA[cur][k][r0 + 4];
            float4 wv = *(const float4*)&sB[cur][k][c0];
            u64 wb0 = pack2(wv.x), wb1 = pack2(wv.y);
            u64 wb2 = pack2(wv.z), wb3 = pack2(wv.w);
            u64 ap0 = aP01.x, ap1 = aP01.y, ap2 = aP23.x, ap3 = aP23.y;
            acc[0][0] = ffma2(ap0, wb0, acc[0][0]);
            acc[0][1] = ffma2(ap0, wb1, acc[0][1]);
            acc[0][2] = ffma2(ap0, wb2, acc[0][2]);
            acc[0][3] = ffma2(ap0, wb3, acc[0][3]);
            acc[1][0] = ffma2(ap1, wb0, acc[1][0]);
            acc[1][1] = ffma2(ap1, wb1, acc[1][1]);
            acc[1][2] = ffma2(ap1, wb2, acc[1][2]);
            acc[1][3] = ffma2(ap1, wb3, acc[1][3]);
            acc[2][0] = ffma2(ap2, wb0, acc[2][0]);
            acc[2][1] = ffma2(ap2, wb1, acc[2][1]);
            acc[2][2] = ffma2(ap2, wb2, acc[2][2]);
            acc[2][3] = ffma2(ap2, wb3, acc[2][3]);
            acc[3][0] = ffma2(ap3, wb0, acc[3][0]);
            acc[3][1] = ffma2(ap3, wb1, acc[3][1]);
            acc[3][2] = ffma2(ap3, wb2, acc[3][2]);
            acc[3][3] = ffma2(ap3, wb3, acc[3][3]);
        }

        if (more) {
            sA[nxt][la_k + 0][la_row0] = na0.x;
            sA[nxt][la_k + 1][la_row0] = na0.y;
            sA[nxt][la_k + 2][la_row0] = na0.z;
            sA[nxt][la_k + 3][la_row0] = na0.w;
            sA[nxt][la_k + 0][la_row0 + 64] = na1.x;
            sA[nxt][la_k + 1][la_row0 + 64] = na1.y;
            sA[nxt][la_k + 2][la_row0 + 64] = na1.z;
            sA[nxt][la_k + 3][la_row0 + 64] = na1.w;
            *(float4*)&sB[nxt][lb_k][lb_n] = nb;
            __syncthreads();
        }
    }

    // epilogue: bias + relu + vectorized stores (one float4 per row)
    const float4 bv = *(const float4*)&bias[c0];
    #pragma unroll
    for (int rp = 0; rp < 4; ++rp) {
        float2 p0 = unpk(acc[rp][0]);
        float2 p1 = unpk(acc[rp][1]);
        float2 p2 = unpk(acc[rp][2]);
        float2 p3 = unpk(acc[rp][3]);
        float4 vlo = make_float4(p0.x + bv.x, p1.x + bv.y, p2.x + bv.z, p3.x + bv.w);
        float4 vhi = make_float4(p0.y + bv.x, p1.y + bv.y, p2.y + bv.z, p3.y + bv.w);
        if (do_relu) {
            vlo.x = fmaxf(vlo.x, 0.f); vlo.y = fmaxf(vlo.y, 0.f);
            vlo.z = fmaxf(vlo.z, 0.f); vlo.w = fmaxf(vlo.w, 0.f);
            vhi.x = fmaxf(vhi.x, 0.f); vhi.y = fmaxf(vhi.y, 0.f);
            vhi.z = fmaxf(vhi.z, 0.f); vhi.w = fmaxf(vhi.w, 0.f);
        }
        const int rowE = blockRow + r0 + rp * 2;
        if (rowE < nrows)
            *(float4*)&out[(size_t)rowE * D + c0] = vlo;
        if (rowE + 1 < nrows)
            *(float4*)&out[(size_t)(rowE + 1) * D + c0] = vhi;
    }
}

__global__ void __launch_bounds__(NTHREADS)
enc_gemm_kernel(const float* __restrict__ feat, const float* __restrict__ W,
                const float* __restrict__ b, int row_off, int nrows, int K) {
    gemm_body(feat, W, b, g_enc + (size_t)row_off * D, nrows, K, 1);
}

__global__ void __launch_bounds__(NTHREADS)
gcn_gemm_kernel(const float* __restrict__ W, const float* __restrict__ b,
                int nrows) {
    gemm_body(g_enc, W, b, g_support, nrows, D, 0);
}

// ---------------------------------------------------------------------------
// Scatter: out[dst] += support[src] * w  (16 threads/edge, red.global.add.v4)
// ---------------------------------------------------------------------------
__global__ void scatter_kernel(const int* __restrict__ esrc,
                               const int* __restrict__ edst,
                               const float* __restrict__ ew,
                               float* __restrict__ out, int E) {
    unsigned idx = blockIdx.x * blockDim.x + threadIdx.x;
    int e = idx >> 4;
    int c = idx & 15;
    if (e >= E) return;
    int s = __ldg(&esrc[e]);
    int d = __ldg(&edst[e]);
    float w = __ldg(&ew[e]);
    float4 v = *(const float4*)&g_support[(size_t)s * D + c * 4];
    v.x *= w; v.y *= w; v.z *= w; v.w *= w;
    float* p = &out[(size_t)d * D + c * 4];
    asm volatile("red.global.add.v4.f32 [%0], {%1, %2, %3, %4};"
                 :: "l"(p), "f"(v.x), "f"(v.y), "f"(v.z), "f"(v.w)
                 : "memory");
}

// ---------------------------------------------------------------------------
// Row L2 normalize (warp per row)
// ---------------------------------------------------------------------------
__global__ void normalize_kernel(float* __restrict__ out, int N) {
    int row = blockIdx.x * (blockDim.x >> 5) + (threadIdx.x >> 5);
    int lane = threadIdx.x & 31;
    if (row >= N) return;
    float2 v = *(float2*)&out[(size_t)row * D + lane * 2];
    float s = v.x * v.x + v.y * v.y;
    #pragma unroll
    for (int o = 16; o > 0; o >>= 1) s += __shfl_xor_sync(0xffffffffu, s, o);
    float n = sqrtf(s);
    float sc = 1.0f / fmaxf(n, 1e-12f);
    v.x *= sc; v.y *= sc;
    *(float2*)&out[(size_t)row * D + lane * 2] = v;
}

// ---------------------------------------------------------------------------
// launch
// ---------------------------------------------------------------------------
extern "C" void kernel_launch(void* const* d_in, const int* in_sizes, int n_in,
                              void* d_out, int out_size) {
    const float* feat_a = (const float*)d_in[0];
    const float* W_a    = (const float*)d_in[1];
    const float* b_a    = (const float*)d_in[2];
    const float* feat_b = (const float*)d_in[3];
    const float* W_b    = (const float*)d_in[4];
    const float* b_b    = (const float*)d_in[5];
    const float* feat_c = (const float*)d_in[6];
    const float* W_c    = (const float*)d_in[7];
    const float* b_c    = (const float*)d_in[8];
    const float* gcn_W  = (const float*)d_in[9];
    const float* gcn_b  = (const float*)d_in[10];
    const float* ew     = (const float*)d_in[11];
    const int*   esrc   = (const int*)d_in[12];
    const int*   edst   = (const int*)d_in[13];
    float* out = (float*)d_out;

    const int Ka = in_sizes[1] / D, Na = in_sizes[0] / Ka;
    const int Kb = in_sizes[4] / D, Nb = in_sizes[3] / Kb;
    const int Kc = in_sizes[7] / D, Nc = in_sizes[6] / Kc;
    const int E  = in_sizes[11];
    const int N  = Na + Nb + Nc;

    dim3 blk(NTHREADS);

    // 1) encoders -> g_enc (concat layout)
    enc_gemm_kernel<<<(Na + BM - 1) / BM, blk>>>(feat_a, W_a, b_a, 0, Na, Ka);
    enc_gemm_kernel<<<(Nb + BM - 1) / BM, blk>>>(feat_b, W_b, b_b, Na, Nb, Kb);
    enc_gemm_kernel<<<(Nc + BM - 1) / BM, blk>>>(feat_c, W_c, b_c, Na + Nb, Nc, Kc);

    // 2) gcn linear -> g_support
    gcn_gemm_kernel<<<(N + BM - 1) / BM, blk>>>(gcn_W, gcn_b, N);

    // 3) zero output, then edge scatter-add
    cudaMemsetAsync(d_out, 0, (size_t)out_size * sizeof(float));
    {
        long long threads = (long long)E * 16;
        int grid = (int)((threads + 255) / 256);
        scatter_kernel<<<grid, 256>>>(esrc, edst, ew, out, E);
    }

    // 4) row L2 normalize
    normalize_kernel<<<(N + 7) / 8, 256>>>(out, N);
}

// round 4
// speedup vs baseline: 1.4912x; 1.0456x over previous
#include <cuda_runtime.h>
#include <cuda_bf16.h>
#include <cstdint>

// ---------------------------------------------------------------------------
// NSHE: 3x (feat @ W + b, relu) -> concat -> (enc @ gcnW + gcnb) ->
//       edge gather*w scatter-add -> row L2 normalize
// GEMMs via warp-level mma.sync bf16 (HMMA) with 3-term hi/lo split.
// (tcgen05 unavailable: harness emits compute_103 PTX, no 'a' features.)
// ---------------------------------------------------------------------------

#define D 64
#define MAX_N 200000
#define TM 128
#define TN 64
#define KC 64
#define NTH 256

__device__ float g_enc[(size_t)MAX_N * D];
__device__ float g_support[(size_t)MAX_N * D];

typedef unsigned long long u64;
typedef unsigned int u32;

// smem byte offsets (dynamic smem, 48 KB total)
#define SM_A_HI 0
#define SM_A_LO 16384
#define SM_B_HI 32768
#define SM_B_LO 40960
#define SM_TOTAL 49152

__device__ __forceinline__ u32 smem_u32(const void* p) {
    u32 a;
    asm("{ .reg .u64 t; cvta.to.shared.u64 t, %1; cvt.u32.u64 %0, t; }"
        : "=r"(a) : "l"(p));
    return a;
}

// pack truncated-bf16 of two fp32: result = [hi16(b) : hi16(a)]
__device__ __forceinline__ u32 hipack(u32 a, u32 b) {
    u32 r;
    asm("prmt.b32 %0, %1, %2, 0x7632;" : "=r"(r) : "r"(a), "r"(b));
    return r;
}
// pack RN bf16 of two residuals: lo16 = x, hi16 = y
__device__ __forceinline__ u32 lopack(float x, float y) {
    u32 r;
    asm("cvt.rn.bf16x2.f32 %0, %1, %2;" : "=r"(r) : "f"(y), "f"(x));
    return r;
}

__device__ __forceinline__ void ldm_x4(u32* r, u32 addr) {
    asm volatile("ldmatrix.sync.aligned.m8n8.x4.shared.b16 {%0,%1,%2,%3}, [%4];"
                 : "=r"(r[0]), "=r"(r[1]), "=r"(r[2]), "=r"(r[3]) : "r"(addr));
}
__device__ __forceinline__ void ldm_x2(u32* r, u32 addr) {
    asm volatile("ldmatrix.sync.aligned.m8n8.x2.shared.b16 {%0,%1}, [%2];"
                 : "=r"(r[0]), "=r"(r[1]) : "r"(addr));
}
__device__ __forceinline__ void mma16816(float* c, const u32* a, const u32* b) {
    asm volatile(
        "mma.sync.aligned.m16n8k16.row.col.f32.bf16.bf16.f32 "
        "{%0,%1,%2,%3}, {%4,%5,%6,%7}, {%8,%9}, {%0,%1,%2,%3};"
        : "+f"(c[0]), "+f"(c[1]), "+f"(c[2]), "+f"(c[3])
        : "r"(a[0]), "r"(a[1]), "r"(a[2]), "r"(a[3]), "r"(b[0]), "r"(b[1]));
}

// swizzled address inside a tile with 128B rows (16B-chunk xor by row&7)
__device__ __forceinline__ u32 swaddr(u32 base, int row, int chunk) {
    return base + row * 128 + (((u32)chunk ^ (row & 7)) << 4);
}

// ---------------------------------------------------------------------------
// HMMA GEMM: out[TM x 64 tile] = act(feat[TM x K] @ W[K x 64] + b)
// ---------------------------------------------------------------------------
__global__ void __launch_bounds__(NTH)
tc_gemm_kernel(const float* __restrict__ feat, const float* __restrict__ W,
               const float* __restrict__ bias, float* __restrict__ out,
               int nrows, int K, int do_relu) {
    extern __shared__ __align__(128) char smem[];
    const u32 sbase = smem_u32(smem);
    const u32 sAhi = sbase + SM_A_HI, sAlo = sbase + SM_A_LO;
    const u32 sBhi = sbase + SM_B_HI, sBlo = sbase + SM_B_LO;

    const int tid = threadIdx.x;
    const int wid = tid >> 5;
    const int lane = tid & 31;
    const int wm = wid & 3;       // warp row group (32 rows)
    const int wn = wid >> 2;      // warp col group (32 cols)
    const int blockRow = blockIdx.x * TM;

    float acc[2][4][4];
    #pragma unroll
    for (int mt = 0; mt < 2; ++mt)
        #pragma unroll
        for (int j = 0; j < 4; ++j)
            #pragma unroll
            for (int q = 0; q < 4; ++q) acc[mt][j][q] = 0.f;

    const int nchunks = K / KC;
    for (int ch = 0; ch < nchunks; ++ch) {
        const int kc = ch * KC;
        __syncthreads();

        // ---- A tile: 128 rows x 64 k fp32 -> hi/lo bf16 swizzled ----
        #pragma unroll
        for (int i = 0; i < 8; ++i) {
            const int p = tid + i * NTH;
            const int row = p >> 4;
            const int c4 = p & 15;             // float4 index along k
            const int rg = min(blockRow + row, nrows - 1);
            const float4 f = *(const float4*)&feat[(size_t)rg * K + kc + c4 * 4];
            const u32 bx = __float_as_uint(f.x), by = __float_as_uint(f.y);
            const u32 bz = __float_as_uint(f.z), bw = __float_as_uint(f.w);
            const u64 hv = ((u64)hipack(bz, bw) << 32) | hipack(bx, by);
            const float lx = f.x - __uint_as_float(bx & 0xFFFF0000u);
            const float ly = f.y - __uint_as_float(by & 0xFFFF0000u);
            const float lz = f.z - __uint_as_float(bz & 0xFFFF0000u);
            const float lw = f.w - __uint_as_float(bw & 0xFFFF0000u);
            const u64 lv = ((u64)lopack(lz, lw) << 32) | lopack(lx, ly);
            const u32 a = swaddr(0, row, c4 >> 1) + (c4 & 1) * 8;
            *(u64*)(smem + SM_A_HI + a) = hv;
            *(u64*)(smem + SM_A_LO + a) = lv;
        }

        // ---- B tile: W[kc..kc+63][0..63] -> transposed [n][k] hi/lo ----
        #pragma unroll
        for (int i = 0; i < 8; ++i) {
            const int p = tid + i * NTH;
            const int n = p & 63;
            const int k0 = (p >> 6) * 2;
            const float w0 = W[(size_t)(kc + k0) * D + n];
            const float w1 = W[(size_t)(kc + k0 + 1) * D + n];
            const u32 b0 = __float_as_uint(w0), b1 = __float_as_uint(w1);
            const float l0 = w0 - __uint_as_float(b0 & 0xFFFF0000u);
            const float l1 = w1 - __uint_as_float(b1 & 0xFFFF0000u);
            const u32 a = swaddr(0, n, k0 >> 3) + (k0 & 7) * 2;
            *(u32*)(smem + SM_B_HI + a) = hipack(b0, b1);
            *(u32*)(smem + SM_B_LO + a) = lopack(l0, l1);
        }
        __syncthreads();

        // ---- compute: 4 k16 steps ----
        #pragma unroll
        for (int ks = 0; ks < 4; ++ks) {
            u32 ah[2][4], al[2][4];
            #pragma unroll
            for (int mt = 0; mt < 2; ++mt) {
                const int row = wm * 32 + mt * 16 + (lane & 15);
                const int chunk = ks * 2 + (lane >> 4);
                ldm_x4(ah[mt], swaddr(sAhi, row, chunk));
                ldm_x4(al[mt], swaddr(sAlo, row, chunk));
            }
            u32 bh[4][2], bl[4][2];
            #pragma unroll
            for (int j = 0; j < 4; ++j) {
                const int row = (wn * 4 + j) * 8 + (lane & 7);
                const int chunk = ks * 2 + ((lane >> 3) & 1);
                ldm_x2(bh[j], swaddr(sBhi, row, chunk));
                ldm_x2(bl[j], swaddr(sBlo, row, chunk));
            }
            #pragma unroll
            for (int mt = 0; mt < 2; ++mt)
                #pragma unroll
                for (int j = 0; j < 4; ++j) {
                    mma16816(acc[mt][j], ah[mt], bh[j]);
                    mma16816(acc[mt][j], ah[mt], bl[j]);
                    mma16816(acc[mt][j], al[mt], bh[j]);
                }
        }
    }

    // ---- epilogue: bias + relu + float2 stores ----
    #pragma unroll
    for (int mt = 0; mt < 2; ++mt) {
        #pragma unroll
        for (int h = 0; h < 2; ++h) {
            const int row = blockRow + wm * 32 + mt * 16 + h * 8 + (lane >> 2);
            if (row >= nrows) continue;
            #pragma unroll
            for (int j = 0; j < 4; ++j) {
                const int n0 = wn * 32 + j * 8 + (lane & 3) * 2;
                float2 v;
                v.x = acc[mt][j][h * 2 + 0] + bias[n0];
                v.y = acc[mt][j][h * 2 + 1] + bias[n0 + 1];
                if (do_relu) { v.x = fmaxf(v.x, 0.f); v.y = fmaxf(v.y, 0.f); }
                *(float2*)&out[(size_t)row * D + n0] = v;
            }
        }
    }
}

// ---------------------------------------------------------------------------
// Scatter: out[dst] += support[src] * w  (16 threads/edge, red.global.add.v4)
// ---------------------------------------------------------------------------
__global__ void scatter_kernel(const int* __restrict__ esrc,
                               const int* __restrict__ edst,
                               const float* __restrict__ ew,
                               float* __restrict__ out, int E) {
    unsigned idx = blockIdx.x * blockDim.x + threadIdx.x;
    int e = idx >> 4;
    int c = idx & 15;
    if (e >= E) return;
    int s = __ldg(&esrc[e]);
    int d = __ldg(&edst[e]);
    float w = __ldg(&ew[e]);
    float4 v = *(const float4*)&g_support[(size_t)s * D + c * 4];
    v.x *= w; v.y *= w; v.z *= w; v.w *= w;
    float* p = &out[(size_t)d * D + c * 4];
    asm volatile("red.global.add.v4.f32 [%0], {%1, %2, %3, %4};"
                 :: "l"(p), "f"(v.x), "f"(v.y), "f"(v.z), "f"(v.w)
                 : "memory");
}

// ---------------------------------------------------------------------------
// Row L2 normalize (warp per row)
// ---------------------------------------------------------------------------
__global__ void normalize_kernel(float* __restrict__ out, int N) {
    int row = blockIdx.x * (blockDim.x >> 5) + (threadIdx.x >> 5);
    int lane = threadIdx.x & 31;
    if (row >= N) return;
    float2 v = *(float2*)&out[(size_t)row * D + lane * 2];
    float s = v.x * v.x + v.y * v.y;
    #pragma unroll
    for (int o = 16; o > 0; o >>= 1) s += __shfl_xor_sync(0xffffffffu, s, o);
    float n = sqrtf(s);
    float sc = 1.0f / fmaxf(n, 1e-12f);
    v.x *= sc; v.y *= sc;
    *(float2*)&out[(size_t)row * D + lane * 2] = v;
}

// ---------------------------------------------------------------------------
// launch
// ---------------------------------------------------------------------------
extern "C" void kernel_launch(void* const* d_in, const int* in_sizes, int n_in,
                              void* d_out, int out_size) {
    const float* feat_a = (const float*)d_in[0];
    const float* W_a    = (const float*)d_in[1];
    const float* b_a    = (const float*)d_in[2];
    const float* feat_b = (const float*)d_in[3];
    const float* W_b    = (const float*)d_in[4];
    const float* b_b    = (const float*)d_in[5];
    const float* feat_c = (const float*)d_in[6];
    const float* W_c    = (const float*)d_in[7];
    const float* b_c    = (const float*)d_in[8];
    const float* gcn_W  = (const float*)d_in[9];
    const float* gcn_b  = (const float*)d_in[10];
    const float* ew     = (const float*)d_in[11];
    const int*   esrc   = (const int*)d_in[12];
    const int*   edst   = (const int*)d_in[13];
    float* out = (float*)d_out;

    const int Ka = in_sizes[1] / D, Na = in_sizes[0] / Ka;
    const int Kb = in_sizes[4] / D, Nb = in_sizes[3] / Kb;
    const int Kc = in_sizes[7] / D, Nc = in_sizes[6] / Kc;
    const int E  = in_sizes[11];
    const int N  = Na + Nb + Nc;

    float* enc;
    float* support;
    cudaGetSymbolAddress((void**)&enc, g_enc);
    cudaGetSymbolAddress((void**)&support, g_support);

    cudaFuncSetAttribute(tc_gemm_kernel,
                         cudaFuncAttributeMaxDynamicSharedMemorySize, SM_TOTAL);

    // 1) encoders -> g_enc (concat layout)
    tc_gemm_kernel<<<(Na + TM - 1) / TM, NTH, SM_TOTAL>>>(
        feat_a, W_a, b_a, enc, Na, Ka, 1);
    tc_gemm_kernel<<<(Nb + TM - 1) / TM, NTH, SM_TOTAL>>>(
        feat_b, W_b, b_b, enc + (size_t)Na * D, Nb, Kb, 1);
    tc_gemm_kernel<<<(Nc + TM - 1) / TM, NTH, SM_TOTAL>>>(
        feat_c, W_c, b_c, enc + (size_t)(Na + Nb) * D, Nc, Kc, 1);

    // 2) gcn linear -> g_support
    tc_gemm_kernel<<<(N + TM - 1) / TM, NTH, SM_TOTAL>>>(
        enc, gcn_W, gcn_b, support, N, D, 0);

    // 3) zero output, then edge scatter-add
    cudaMemsetAsync(d_out, 0, (size_t)out_size * sizeof(float));
    {
        long long threads = (long long)E * 16;
        int grid = (int)((threads + 255) / 256);
        scatter_kernel<<<grid, 256>>>(esrc, edst, ew, out, E);
    }

    // 4) row L2 normalize
    normalize_kernel<<<(N + 7) / 8, 256>>>(out, N);
}

// round 5
// speedup vs baseline: 1.4946x; 1.0023x over previous
#include <cuda_runtime.h>
#include <cuda_bf16.h>
#include <cstdint>

// ---------------------------------------------------------------------------
// NSHE: 3x (feat @ W + b, relu) -> concat -> (enc @ gcnW + gcnb) ->
//       edge gather*w scatter-add -> row L2 normalize
// GEMMs via warp-level mma.sync bf16 (HMMA) with 3-term hi/lo split.
// (tcgen05 unavailable: harness emits compute_103 PTX, no 'a' features.)
// ---------------------------------------------------------------------------

#define D 64
#define MAX_N 200000
#define TM 128
#define TN 64
#define KC 64
#define NTH 256

__device__ float g_enc[(size_t)MAX_N * D];
__device__ float g_support[(size_t)MAX_N * D];

typedef unsigned long long u64;
typedef unsigned int u32;

// smem byte offsets (dynamic smem, 48 KB total)
#define SM_A_HI 0
#define SM_A_LO 16384
#define SM_B_HI 32768
#define SM_B_LO 40960
#define SM_TOTAL 49152

__device__ __forceinline__ u32 smem_u32(const void* p) {
    u32 a;
    asm("{ .reg .u64 t; cvta.to.shared.u64 t, %1; cvt.u32.u64 %0, t; }"
        : "=r"(a) : "l"(p));
    return a;
}

// pack truncated-bf16 of two fp32: result = [hi16(b) : hi16(a)]
__device__ __forceinline__ u32 hipack(u32 a, u32 b) {
    u32 r;
    asm("prmt.b32 %0, %1, %2, 0x7632;" : "=r"(r) : "r"(a), "r"(b));
    return r;
}
// pack RN bf16 of two residuals: lo16 = x, hi16 = y
__device__ __forceinline__ u32 lopack(float x, float y) {
    u32 r;
    asm("cvt.rn.bf16x2.f32 %0, %1, %2;" : "=r"(r) : "f"(y), "f"(x));
    return r;
}

__device__ __forceinline__ void ldm_x4(u32* r, u32 addr) {
    asm volatile("ldmatrix.sync.aligned.m8n8.x4.shared.b16 {%0,%1,%2,%3}, [%4];"
                 : "=r"(r[0]), "=r"(r[1]), "=r"(r[2]), "=r"(r[3]) : "r"(addr));
}
__device__ __forceinline__ void ldm_x2(u32* r, u32 addr) {
    asm volatile("ldmatrix.sync.aligned.m8n8.x2.shared.b16 {%0,%1}, [%2];"
                 : "=r"(r[0]), "=r"(r[1]) : "r"(addr));
}
__device__ __forceinline__ void mma16816(float* c, const u32* a, const u32* b) {
    asm volatile(
        "mma.sync.aligned.m16n8k16.row.col.f32.bf16.bf16.f32 "
        "{%0,%1,%2,%3}, {%4,%5,%6,%7}, {%8,%9}, {%0,%1,%2,%3};"
        : "+f"(c[0]), "+f"(c[1]), "+f"(c[2]), "+f"(c[3])
        : "r"(a[0]), "r"(a[1]), "r"(a[2]), "r"(a[3]), "r"(b[0]), "r"(b[1]));
}

// swizzled address inside a tile with 128B rows (16B-chunk xor by row&7)
__device__ __forceinline__ u32 swaddr(u32 base, int row, int chunk) {
    return base + row * 128 + (((u32)chunk ^ (row & 7)) << 4);
}

// ---------------------------------------------------------------------------
// HMMA GEMM: out[TM x 64 tile] = act(feat[TM x K] @ W[K x 64] + b)
// ---------------------------------------------------------------------------
__global__ void __launch_bounds__(NTH)
tc_gemm_kernel(const float* __restrict__ feat, const float* __restrict__ W,
               const float* __restrict__ bias, float* __restrict__ out,
               int nrows, int K, int do_relu) {
    extern __shared__ __align__(128) char smem[];
    const u32 sbase = smem_u32(smem);
    const u32 sAhi = sbase + SM_A_HI, sAlo = sbase + SM_A_LO;
    const u32 sBhi = sbase + SM_B_HI, sBlo = sbase + SM_B_LO;

    const int tid = threadIdx.x;
    const int wid = tid >> 5;
    const int lane = tid & 31;
    const int wm = wid & 3;       // warp row group (32 rows)
    const int wn = wid >> 2;      // warp col group (32 cols)
    const int blockRow = blockIdx.x * TM;

    float acc[2][4][4];
    #pragma unroll
    for (int mt = 0; mt < 2; ++mt)
        #pragma unroll
        for (int j = 0; j < 4; ++j)
            #pragma unroll
            for (int q = 0; q < 4; ++q) acc[mt][j][q] = 0.f;

    const int nchunks = K / KC;
    for (int ch = 0; ch < nchunks; ++ch) {
        const int kc = ch * KC;
        __syncthreads();

        // ---- A tile: 128 rows x 64 k fp32 -> hi/lo bf16 swizzled ----
        #pragma unroll
        for (int i = 0; i < 8; ++i) {
            const int p = tid + i * NTH;
            const int row = p >> 4;
            const int c4 = p & 15;             // float4 index along k
            const int rg = min(blockRow + row, nrows - 1);
            const float4 f = *(const float4*)&feat[(size_t)rg * K + kc + c4 * 4];
            const u32 bx = __float_as_uint(f.x), by = __float_as_uint(f.y);
            const u32 bz = __float_as_uint(f.z), bw = __float_as_uint(f.w);
            const u64 hv = ((u64)hipack(bz, bw) << 32) | hipack(bx, by);
            const float lx = f.x - __uint_as_float(bx & 0xFFFF0000u);
            const float ly = f.y - __uint_as_float(by & 0xFFFF0000u);
            const float lz = f.z - __uint_as_float(bz & 0xFFFF0000u);
            const float lw = f.w - __uint_as_float(bw & 0xFFFF0000u);
            const u64 lv = ((u64)lopack(lz, lw) << 32) | lopack(lx, ly);
            const u32 a = swaddr(0, row, c4 >> 1) + (c4 & 1) * 8;
            *(u64*)(smem + SM_A_HI + a) = hv;
            *(u64*)(smem + SM_A_LO + a) = lv;
        }

        // ---- B tile: W[kc..kc+63][0..63] -> transposed [n][k] hi/lo ----
        #pragma unroll
        for (int i = 0; i < 8; ++i) {
            const int p = tid + i * NTH;
            const int n = p & 63;
            const int k0 = (p >> 6) * 2;
            const float w0 = W[(size_t)(kc + k0) * D + n];
            const float w1 = W[(size_t)(kc + k0 + 1) * D + n];
            const u32 b0 = __float_as_uint(w0), b1 = __float_as_uint(w1);
            const float l0 = w0 - __uint_as_float(b0 & 0xFFFF0000u);
            const float l1 = w1 - __uint_as_float(b1 & 0xFFFF0000u);
            const u32 a = swaddr(0, n, k0 >> 3) + (k0 & 7) * 2;
            *(u32*)(smem + SM_B_HI + a) = hipack(b0, b1);
            *(u32*)(smem + SM_B_LO + a) = lopack(l0, l1);
        }
        __syncthreads();

        // ---- compute: 4 k16 steps ----
        #pragma unroll
        for (int ks = 0; ks < 4; ++ks) {
            u32 ah[2][4], al[2][4];
            #pragma unroll
            for (int mt = 0; mt < 2; ++mt) {
                const int row = wm * 32 + mt * 16 + (lane & 15);
                const int chunk = ks * 2 + (lane >> 4);
                ldm_x4(ah[mt], swaddr(sAhi, row, chunk));
                ldm_x4(al[mt], swaddr(sAlo, row, chunk));
            }
            u32 bh[4][2], bl[4][2];
            #pragma unroll
            for (int j = 0; j < 4; ++j) {
                const int row = (wn * 4 + j) * 8 + (lane & 7);
                const int chunk = ks * 2 + ((lane >> 3) & 1);
                ldm_x2(bh[j], swaddr(sBhi, row, chunk));
                ldm_x2(bl[j], swaddr(sBlo, row, chunk));
            }
            #pragma unroll
            for (int mt = 0; mt < 2; ++mt)
                #pragma unroll
                for (int j = 0; j < 4; ++j) {
                    mma16816(acc[mt][j], ah[mt], bh[j]);
                    mma16816(acc[mt][j], ah[mt], bl[j]);
                    mma16816(acc[mt][j], al[mt], bh[j]);
                }
        }
    }

    // ---- epilogue: bias + relu + float2 stores ----
    #pragma unroll
    for (int mt = 0; mt < 2; ++mt) {
        #pragma unroll
        for (int h = 0; h < 2; ++h) {
            const int row = blockRow + wm * 32 + mt * 16 + h * 8 + (lane >> 2);
            if (row >= nrows) continue;
            #pragma unroll
            for (int j = 0; j < 4; ++j) {
                const int n0 = wn * 32 + j * 8 + (lane & 3) * 2;
                float2 v;
                v.x = acc[mt][j][h * 2 + 0] + bias[n0];
                v.y = acc[mt][j][h * 2 + 1] + bias[n0 + 1];
                if (do_relu) { v.x = fmaxf(v.x, 0.f); v.y = fmaxf(v.y, 0.f); }
                *(float2*)&out[(size_t)row * D + n0] = v;
            }
        }
    }
}

// ---------------------------------------------------------------------------
// Scatter: out[dst] += support[src] * w  (16 threads/edge, red.global.add.v4)
// ---------------------------------------------------------------------------
__global__ void scatter_kernel(const int* __restrict__ esrc,
                               const int* __restrict__ edst,
                               const float* __restrict__ ew,
                               float* __restrict__ out, int E) {
    unsigned idx = blockIdx.x * blockDim.x + threadIdx.x;
    int e = idx >> 4;
    int c = idx & 15;
    if (e >= E) return;
    int s = __ldg(&esrc[e]);
    int d = __ldg(&edst[e]);
    float w = __ldg(&ew[e]);
    float4 v = *(const float4*)&g_support[(size_t)s * D + c * 4];
    v.x *= w; v.y *= w; v.z *= w; v.w *= w;
    float* p = &out[(size_t)d * D + c * 4];
    asm volatile("red.global.add.v4.f32 [%0], {%1, %2, %3, %4};"
                 :: "l"(p), "f"(v.x), "f"(v.y), "f"(v.z), "f"(v.w)
                 : "memory");
}

// ---------------------------------------------------------------------------
// Row L2 normalize (warp per row)
// ---------------------------------------------------------------------------
__global__ void normalize_kernel(float* __restrict__ out, int N) {
    int row = blockIdx.x * (blockDim.x >> 5) + (threadIdx.x >> 5);
    int lane = threadIdx.x & 31;
    if (row >= N) return;
    float2 v = *(float2*)&out[(size_t)row * D + lane * 2];
    float s = v.x * v.x + v.y * v.y;
    #pragma unroll
    for (int o = 16; o > 0; o >>= 1) s += __shfl_xor_sync(0xffffffffu, s, o);
    float n = sqrtf(s);
    float sc = 1.0f / fmaxf(n, 1e-12f);
    v.x *= sc; v.y *= sc;
    *(float2*)&out[(size_t)row * D + lane * 2] = v;
}

// ---------------------------------------------------------------------------
// launch
// ---------------------------------------------------------------------------
extern "C" void kernel_launch(void* const* d_in, const int* in_sizes, int n_in,
                              void* d_out, int out_size) {
    const float* feat_a = (const float*)d_in[0];
    const float* W_a    = (const float*)d_in[1];
    const float* b_a    = (const float*)d_in[2];
    const float* feat_b = (const float*)d_in[3];
    const float* W_b    = (const float*)d_in[4];
    const float* b_b    = (const float*)d_in[5];
    const float* feat_c = (const float*)d_in[6];
    const float* W_c    = (const float*)d_in[7];
    const float* b_c    = (const float*)d_in[8];
    const float* gcn_W  = (const float*)d_in[9];
    const float* gcn_b  = (const float*)d_in[10];
    const float* ew     = (const float*)d_in[11];
    const int*   esrc   = (const int*)d_in[12];
    const int*   edst   = (const int*)d_in[13];
    float* out = (float*)d_out;

    const int Ka = in_sizes[1] / D, Na = in_sizes[0] / Ka;
    const int Kb = in_sizes[4] / D, Nb = in_sizes[3] / Kb;
    const int Kc = in_sizes[7] / D, Nc = in_sizes[6] / Kc;
    const int E  = in_sizes[11];
    const int N  = Na + Nb + Nc;

    float* enc;
    float* support;
    cudaGetSymbolAddress((void**)&enc, g_enc);
    cudaGetSymbolAddress((void**)&support, g_support);

    cudaFuncSetAttribute(tc_gemm_kernel,
                         cudaFuncAttributeMaxDynamicSharedMemorySize, SM_TOTAL);

    // 1) encoders -> g_enc (concat layout)
    tc_gemm_kernel<<<(Na + TM - 1) / TM, NTH, SM_TOTAL>>>(
        feat_a, W_a, b_a, enc, Na, Ka, 1);
    tc_gemm_kernel<<<(Nb + TM - 1) / TM, NTH, SM_TOTAL>>>(
        feat_b, W_b, b_b, enc + (size_t)Na * D, Nb, Kb, 1);
    tc_gemm_kernel<<<(Nc + TM - 1) / TM, NTH, SM_TOTAL>>>(
        feat_c, W_c, b_c, enc + (size_t)(Na + Nb) * D, Nc, Kc, 1);

    // 2) gcn linear -> g_support
    tc_gemm_kernel<<<(N + TM - 1) / TM, NTH, SM_TOTAL>>>(
        enc, gcn_W, gcn_b, support, N, D, 0);

    // 3) zero output, then edge scatter-add
    cudaMemsetAsync(d_out, 0, (size_t)out_size * sizeof(float));
    {
        long long threads = (long long)E * 16;
        int grid = (int)((threads + 255) / 256);
        scatter_kernel<<<grid, 256>>>(esrc, edst, ew, out, E);
    }

    // 4) row L2 normalize
    normalize_kernel<<<(N + 7) / 8, 256>>>(out, N);
}

// round 6
// speedup vs baseline: 1.9045x; 1.2742x over previous
#include <cuda_runtime.h>
#include <cuda_bf16.h>
#include <cstdint>

// ---------------------------------------------------------------------------
// NSHE: 3x (feat @ W + b, relu) -> concat -> (enc @ gcnW + gcnb) ->
//       edge gather*w scatter-add -> row L2 normalize
// GEMMs via warp-level mma.sync bf16 (HMMA) with 3-term hi/lo split.
// ---------------------------------------------------------------------------

#define D 64
#define MAX_N 200000
#define TM 128
#define KC 64
#define NTH 256

__device__ float g_enc[(size_t)MAX_N * D];
__device__ float g_support[(size_t)MAX_N * D];

typedef unsigned long long u64;
typedef unsigned int u32;

// smem byte offsets (dynamic smem, 48 KB total)
#define SM_A_HI 0
#define SM_A_LO 16384
#define SM_B_HI 32768
#define SM_B_LO 40960
#define SM_TOTAL 49152

__device__ __forceinline__ u32 smem_u32(const void* p) {
    u32 a;
    asm("{ .reg .u64 t; cvta.to.shared.u64 t, %1; cvt.u32.u64 %0, t; }"
        : "=r"(a) : "l"(p));
    return a;
}

// pack truncated-bf16 of two fp32: result = [hi16(b) : hi16(a)]
__device__ __forceinline__ u32 hipack(u32 a, u32 b) {
    u32 r;
    asm("prmt.b32 %0, %1, %2, 0x7632;" : "=r"(r) : "r"(a), "r"(b));
    return r;
}
// pack RN bf16 of two residuals: lo16 = x, hi16 = y
__device__ __forceinline__ u32 lopack(float x, float y) {
    u32 r;
    asm("cvt.rn.bf16x2.f32 %0, %1, %2;" : "=r"(r) : "f"(y), "f"(x));
    return r;
}

__device__ __forceinline__ void ldm_x4(u32* r, u32 addr) {
    asm volatile("ldmatrix.sync.aligned.m8n8.x4.shared.b16 {%0,%1,%2,%3}, [%4];"
                 : "=r"(r[0]), "=r"(r[1]), "=r"(r[2]), "=r"(r[3]) : "r"(addr));
}
__device__ __forceinline__ void ldm_x2(u32* r, u32 addr) {
    asm volatile("ldmatrix.sync.aligned.m8n8.x2.shared.b16 {%0,%1}, [%2];"
                 : "=r"(r[0]), "=r"(r[1]) : "r"(addr));
}
__device__ __forceinline__ void mma16816(float* c, const u32* a, const u32* b) {
    asm volatile(
        "mma.sync.aligned.m16n8k16.row.col.f32.bf16.bf16.f32 "
        "{%0,%1,%2,%3}, {%4,%5,%6,%7}, {%8,%9}, {%0,%1,%2,%3};"
        : "+f"(c[0]), "+f"(c[1]), "+f"(c[2]), "+f"(c[3])
        : "r"(a[0]), "r"(a[1]), "r"(a[2]), "r"(a[3]), "r"(b[0]), "r"(b[1]));
}

// swizzled address inside a tile with 128B rows (16B-chunk xor by row&7)
__device__ __forceinline__ u32 swaddr(u32 base, int row, int chunk) {
    return base + row * 128 + (((u32)chunk ^ (row & 7)) << 4);
}

// ---------------------------------------------------------------------------
// HMMA GEMM body: out[TM x 64 tile at blockRow] = act(feat @ W + b)
// ---------------------------------------------------------------------------
__device__ __forceinline__ void gemm_body(const float* __restrict__ feat,
                                          const float* __restrict__ W,
                                          const float* __restrict__ bias,
                                          float* __restrict__ out,
                                          int nrows, int K, int do_relu,
                                          int blockRow, char* smem) {
    const u32 sbase = smem_u32(smem);
    const u32 sAhi = sbase + SM_A_HI, sAlo = sbase + SM_A_LO;
    const u32 sBhi = sbase + SM_B_HI, sBlo = sbase + SM_B_LO;

    const int tid = threadIdx.x;
    const int wid = tid >> 5;
    const int lane = tid & 31;
    const int wm = wid & 3;       // warp row group (32 rows)
    const int wn = wid >> 2;      // warp col group (32 cols)

    float acc[2][4][4];
    #pragma unroll
    for (int mt = 0; mt < 2; ++mt)
        #pragma unroll
        for (int j = 0; j < 4; ++j)
            #pragma unroll
            for (int q = 0; q < 4; ++q) acc[mt][j][q] = 0.f;

    const int nchunks = K / KC;
    for (int ch = 0; ch < nchunks; ++ch) {
        const int kc = ch * KC;
        __syncthreads();

        // ---- A tile: 128 rows x 64 k fp32 -> hi/lo bf16 swizzled ----
        #pragma unroll
        for (int i = 0; i < 8; ++i) {
            const int p = tid + i * NTH;
            const int row = p >> 4;
            const int c4 = p & 15;             // float4 index along k
            const int rg = min(blockRow + row, nrows - 1);
            const float4 f = *(const float4*)&feat[(size_t)rg * K + kc + c4 * 4];
            const u32 bx = __float_as_uint(f.x), by = __float_as_uint(f.y);
            const u32 bz = __float_as_uint(f.z), bw = __float_as_uint(f.w);
            const u64 hv = ((u64)hipack(bz, bw) << 32) | hipack(bx, by);
            const float lx = f.x - __uint_as_float(bx & 0xFFFF0000u);
            const float ly = f.y - __uint_as_float(by & 0xFFFF0000u);
            const float lz = f.z - __uint_as_float(bz & 0xFFFF0000u);
            const float lw = f.w - __uint_as_float(bw & 0xFFFF0000u);
            const u64 lv = ((u64)lopack(lz, lw) << 32) | lopack(lx, ly);
            const u32 a = swaddr(0, row, c4 >> 1) + (c4 & 1) * 8;
            *(u64*)(smem + SM_A_HI + a) = hv;
            *(u64*)(smem + SM_A_LO + a) = lv;
        }

        // ---- B tile: W[kc..kc+63][0..63] -> transposed [n][k] hi/lo ----
        #pragma unroll
        for (int i = 0; i < 8; ++i) {
            const int p = tid + i * NTH;
            const int n = p & 63;
            const int k0 = (p >> 6) * 2;
            const float w0 = W[(size_t)(kc + k0) * D + n];
            const float w1 = W[(size_t)(kc + k0 + 1) * D + n];
            const u32 b0 = __float_as_uint(w0), b1 = __float_as_uint(w1);
            const float l0 = w0 - __uint_as_float(b0 & 0xFFFF0000u);
            const float l1 = w1 - __uint_as_float(b1 & 0xFFFF0000u);
            const u32 a = swaddr(0, n, k0 >> 3) + (k0 & 7) * 2;
            *(u32*)(smem + SM_B_HI + a) = hipack(b0, b1);
            *(u32*)(smem + SM_B_LO + a) = lopack(l0, l1);
        }
        __syncthreads();

        // ---- compute: 4 k16 steps ----
        #pragma unroll
        for (int ks = 0; ks < 4; ++ks) {
            u32 ah[2][4], al[2][4];
            #pragma unroll
            for (int mt = 0; mt < 2; ++mt) {
                const int row = wm * 32 + mt * 16 + (lane & 15);
                const int chunk = ks * 2 + (lane >> 4);
                ldm_x4(ah[mt], swaddr(sAhi, row, chunk));
                ldm_x4(al[mt], swaddr(sAlo, row, chunk));
            }
            u32 bh[4][2], bl[4][2];
            #pragma unroll
            for (int j = 0; j < 4; ++j) {
                const int row = (wn * 4 + j) * 8 + (lane & 7);
                const int chunk = ks * 2 + ((lane >> 3) & 1);
                ldm_x2(bh[j], swaddr(sBhi, row, chunk));
                ldm_x2(bl[j], swaddr(sBlo, row, chunk));
            }
            #pragma unroll
            for (int mt = 0; mt < 2; ++mt)
                #pragma unroll
                for (int j = 0; j < 4; ++j) {
                    mma16816(acc[mt][j], ah[mt], bh[j]);
                    mma16816(acc[mt][j], ah[mt], bl[j]);
                    mma16816(acc[mt][j], al[mt], bh[j]);
                }
        }
    }

    // ---- epilogue: bias + relu + float2 stores ----
    #pragma unroll
    for (int mt = 0; mt < 2; ++mt) {
        #pragma unroll
        for (int h = 0; h < 2; ++h) {
            const int row = blockRow + wm * 32 + mt * 16 + h * 8 + (lane >> 2);
            if (row >= nrows) continue;
            #pragma unroll
            for (int j = 0; j < 4; ++j) {
                const int n0 = wn * 32 + j * 8 + (lane & 3) * 2;
                float2 v;
                v.x = acc[mt][j][h * 2 + 0] + bias[n0];
                v.y = acc[mt][j][h * 2 + 1] + bias[n0 + 1];
                if (do_relu) { v.x = fmaxf(v.x, 0.f); v.y = fmaxf(v.y, 0.f); }
                *(float2*)&out[(size_t)row * D + n0] = v;
            }
        }
    }
}

// ---------------------------------------------------------------------------
// Merged encoder kernel: block-range dispatch over the 3 node types
// ---------------------------------------------------------------------------
__global__ void __launch_bounds__(NTH, 2)
enc_all_kernel(const float* __restrict__ fa, const float* __restrict__ Wa,
               const float* __restrict__ ba, int Na, int Ka, int ga,
               const float* __restrict__ fb, const float* __restrict__ Wb,
               const float* __restrict__ bb, int Nb, int Kb, int gb,
               const float* __restrict__ fc, const float* __restrict__ Wc,
               const float* __restrict__ bc, int Nc, int Kc_) {
    extern __shared__ __align__(128) char smem[];
    float* enc = g_enc;
    const int b = blockIdx.x;
    if (b < ga) {
        gemm_body(fa, Wa, ba, enc, Na, Ka, 1, b * TM, smem);
    } else if (b < ga + gb) {
        gemm_body(fb, Wb, bb, enc + (size_t)Na * D, Nb, Kb, 1,
                  (b - ga) * TM, smem);
    } else {
        gemm_body(fc, Wc, bc, enc + (size_t)(Na + Nb) * D, Nc, Kc_, 1,
                  (b - ga - gb) * TM, smem);
    }
}

__global__ void __launch_bounds__(NTH, 2)
gcn_gemm_kernel(const float* __restrict__ W, const float* __restrict__ b,
                int nrows) {
    extern __shared__ __align__(128) char smem[];
    gemm_body(g_enc, W, b, g_support, nrows, D, 0, blockIdx.x * TM, smem);
}

// ---------------------------------------------------------------------------
// Scatter: out[dst] += support[src] * w  (16 threads/edge, red.global.add.v4)
// ---------------------------------------------------------------------------
__global__ void scatter_kernel(const int* __restrict__ esrc,
                               const int* __restrict__ edst,
                               const float* __restrict__ ew,
                               float* __restrict__ out, int E) {
    unsigned idx = blockIdx.x * blockDim.x + threadIdx.x;
    int e = idx >> 4;
    int c = idx & 15;
    if (e >= E) return;
    int s = __ldg(&esrc[e]);
    int d = __ldg(&edst[e]);
    float w = __ldg(&ew[e]);
    float4 v = *(const float4*)&g_support[(size_t)s * D + c * 4];
    v.x *= w; v.y *= w; v.z *= w; v.w *= w;
    float* p = &out[(size_t)d * D + c * 4];
    asm volatile("red.global.add.v4.f32 [%0], {%1, %2, %3, %4};"
                 :: "l"(p), "f"(v.x), "f"(v.y), "f"(v.z), "f"(v.w)
                 : "memory");
}

// ---------------------------------------------------------------------------
// Row L2 normalize (warp per row)
// ---------------------------------------------------------------------------
__global__ void normalize_kernel(float* __restrict__ out, int N) {
    int row = blockIdx.x * (blockDim.x >> 5) + (threadIdx.x >> 5);
    int lane = threadIdx.x & 31;
    if (row >= N) return;
    float2 v = *(float2*)&out[(size_t)row * D + lane * 2];
    float s = v.x * v.x + v.y * v.y;
    #pragma unroll
    for (int o = 16; o > 0; o >>= 1) s += __shfl_xor_sync(0xffffffffu, s, o);
    float n = sqrtf(s);
    float sc = 1.0f / fmaxf(n, 1e-12f);
    v.x *= sc; v.y *= sc;
    *(float2*)&out[(size_t)row * D + lane * 2] = v;
}

// ---------------------------------------------------------------------------
// launch
// ---------------------------------------------------------------------------
extern "C" void kernel_launch(void* const* d_in, const int* in_sizes, int n_in,
                              void* d_out, int out_size) {
    const float* feat_a = (const float*)d_in[0];
    const float* W_a    = (const float*)d_in[1];
    const float* b_a    = (const float*)d_in[2];
    const float* feat_b = (const float*)d_in[3];
    const float* W_b    = (const float*)d_in[4];
    const float* b_b    = (const float*)d_in[5];
    const float* feat_c = (const float*)d_in[6];
    const float* W_c    = (const float*)d_in[7];
    const float* b_c    = (const float*)d_in[8];
    const float* gcn_W  = (const float*)d_in[9];
    const float* gcn_b  = (const float*)d_in[10];
    const float* ew     = (const float*)d_in[11];
    const int*   esrc   = (const int*)d_in[12];
    const int*   edst   = (const int*)d_in[13];
    float* out = (float*)d_out;

    const int Ka = in_sizes[1] / D, Na = in_sizes[0] / Ka;
    const int Kb = in_sizes[4] / D, Nb = in_sizes[3] / Kb;
    const int Kc = in_sizes[7] / D, Nc = in_sizes[6] / Kc;
    const int E  = in_sizes[11];
    const int N  = Na + Nb + Nc;

    const int ga = (Na + TM - 1) / TM;
    const int gb = (Nb + TM - 1) / TM;
    const int gc = (Nc + TM - 1) / TM;

    cudaFuncSetAttribute(enc_all_kernel,
                         cudaFuncAttributeMaxDynamicSharedMemorySize, SM_TOTAL);
    cudaFuncSetAttribute(gcn_gemm_kernel,
                         cudaFuncAttributeMaxDynamicSharedMemorySize, SM_TOTAL);

    // 1) encoders -> g_enc (single merged launch)
    enc_all_kernel<<<ga + gb + gc, NTH, SM_TOTAL>>>(
        feat_a, W_a, b_a, Na, Ka, ga,
        feat_b, W_b, b_b, Nb, Kb, gb,
        feat_c, W_c, b_c, Nc, Kc);

    // 2) gcn linear -> g_support
    gcn_gemm_kernel<<<(N + TM - 1) / TM, NTH, SM_TOTAL>>>(gcn_W, gcn_b, N);

    // 3) zero output, then edge scatter-add
    cudaMemsetAsync(d_out, 0, (size_t)out_size * sizeof(float));
    {
        long long threads = (long long)E * 16;
        int grid = (int)((threads + 255) / 256);
        scatter_kernel<<<grid, 256>>>(esrc, edst, ew, out, E);
    }

    // 4) row L2 normalize
    normalize_kernel<<<(N + 7) / 8, 256>>>(out, N);
}